// round 3
// baseline (speedup 1.0000x reference)
#include <cuda_runtime.h>
#include <cstdint>

// Problem constants (from reference)
#define NN      50000     // N_NODES
#define DIN     128
#define DHID    256
#define DH4     (DHID/4)  // 64 float4 per row

// ---------------------------------------------------------------------------
// Scratch (static device globals — no allocation in kernel_launch)
// ---------------------------------------------------------------------------
__device__ float g_h  [(size_t)NN * DHID];   // GEMM output H = X @ W
__device__ float g_agg[(size_t)NN * DHID];   // aggregation buffer
__device__ float g_x1 [(size_t)NN * DHID];   // layer activation ping buffer
__device__ float g_dinv[NN];                 // deg accumulator -> dinv_sqrt

// ---------------------------------------------------------------------------
// f32x2 packed-FMA helpers (FFMA2 — PTX-only on sm_103a)
// ---------------------------------------------------------------------------
#define FMA2(d, a, b) \
    asm("fma.rn.f32x2 %0, %1, %2, %0;" : "+l"(d) : "l"(a), "l"(b))
#define PACK2(d, lo, hi) \
    asm("mov.b64 %0, {%1, %2};" : "=l"(d) : "f"(lo), "f"(hi))
#define UNPACK2(lo, hi, d) \
    asm("mov.b64 {%0, %1}, %2;" : "=f"(lo), "=f"(hi) : "l"(d))

// Vector f32 reduction to global memory (sm_90+): 1 op = 16 bytes, no return.
__device__ __forceinline__ void red_add_v4(float* addr, float x, float y,
                                           float z, float w) {
    asm volatile("red.global.add.v4.f32 [%0], {%1, %2, %3, %4};"
                 :: "l"(addr), "f"(x), "f"(y), "f"(z), "f"(w) : "memory");
}

// ---------------------------------------------------------------------------
// Degree / normalization
// ---------------------------------------------------------------------------
__global__ void deg_init_kernel(int n) {
    int i = blockIdx.x * blockDim.x + threadIdx.x;
    if (i < n) g_dinv[i] = 1.0f;   // self loop contributes 1 to degree
}

__global__ void deg_count_kernel(const int* __restrict__ dst, int E) {
    int i = blockIdx.x * blockDim.x + threadIdx.x;
    if (i < E) atomicAdd(&g_dinv[dst[i]], 1.0f);
}

__global__ void deg_finish_kernel(int n) {
    int i = blockIdx.x * blockDim.x + threadIdx.x;
    if (i < n) g_dinv[i] = rsqrtf(g_dinv[i]);   // deg >= 1 always
}

// ---------------------------------------------------------------------------
// Fused GEMM + self-loop init:
//   H   = X @ W                       [M, 256]
//   AGG = H * dinv^2 (per row)        (self-loop message pre-seeded)
// Tile: BM=128, BN=128, BK=8, 256 threads, per-thread 8x8 via f32x2 pairs
// over the row dimension (row-pairs load directly as u64 from smem).
// ---------------------------------------------------------------------------
template <int K, bool USE_X1>
__global__ __launch_bounds__(256)
void gemm_agg_kernel(const float* __restrict__ Xin,
                     const float* __restrict__ W, int M) {
    constexpr int BM = 128, BN = 128, BK = 8;
    __shared__ float As[BK][BM];
    __shared__ float Bs[BK][BN];

    const float* __restrict__ X = USE_X1 ? g_x1 : Xin;

    const int tid   = threadIdx.x;
    const int mBase = blockIdx.y * BM;
    const int nBase = blockIdx.x * BN;
    const int ty = tid >> 4;         // 0..15 -> 8 rows each
    const int tx = tid & 15;         // 0..15 -> 8 cols each

    // A-tile load map: 2 threads per row, float4 each
    const int aRow = tid >> 1;
    const int aK   = (tid & 1) * 4;
    // B-tile load map: 32 threads per K-row, float4 each
    const int bK   = tid >> 5;
    const int bCol = (tid & 31) * 4;

    unsigned long long acc[4][8];    // [row-pair][col], packed f32x2 over rows
    #pragma unroll
    for (int ii = 0; ii < 4; ii++)
        #pragma unroll
        for (int j = 0; j < 8; j++) acc[ii][j] = 0ULL;

    for (int k0 = 0; k0 < K; k0 += BK) {
        // load A (X[m, k]) -> As[k][m]
        float4 av = make_float4(0.f, 0.f, 0.f, 0.f);
        int m = mBase + aRow;
        if (m < M)
            av = *reinterpret_cast<const float4*>(X + (size_t)m * K + k0 + aK);
        As[aK + 0][aRow] = av.x;
        As[aK + 1][aRow] = av.y;
        As[aK + 2][aRow] = av.z;
        As[aK + 3][aRow] = av.w;
        // load B (W[k, n]) -> Bs[k][n]
        float4 bv = *reinterpret_cast<const float4*>(
            W + (size_t)(k0 + bK) * DHID + nBase + bCol);
        *reinterpret_cast<float4*>(&Bs[bK][bCol]) = bv;
        __syncthreads();

        #pragma unroll
        for (int k = 0; k < BK; k++) {
            unsigned long long a2[4];
            #pragma unroll
            for (int ii = 0; ii < 4; ii++)
                a2[ii] = *reinterpret_cast<const unsigned long long*>(
                    &As[k][ty * 8 + 2 * ii]);
            float4 b0 = *reinterpret_cast<const float4*>(&Bs[k][tx * 8]);
            float4 b1 = *reinterpret_cast<const float4*>(&Bs[k][tx * 8 + 4]);
            unsigned long long bd[8];
            PACK2(bd[0], b0.x, b0.x);  PACK2(bd[1], b0.y, b0.y);
            PACK2(bd[2], b0.z, b0.z);  PACK2(bd[3], b0.w, b0.w);
            PACK2(bd[4], b1.x, b1.x);  PACK2(bd[5], b1.y, b1.y);
            PACK2(bd[6], b1.z, b1.z);  PACK2(bd[7], b1.w, b1.w);
            #pragma unroll
            for (int ii = 0; ii < 4; ii++)
                #pragma unroll
                for (int j = 0; j < 8; j++)
                    FMA2(acc[ii][j], a2[ii], bd[j]);
        }
        __syncthreads();
    }

    // epilogue: unpack row-pairs, write H and AGG = H * dinv^2
    float v[8][8];
    #pragma unroll
    for (int ii = 0; ii < 4; ii++)
        #pragma unroll
        for (int j = 0; j < 8; j++) {
            float lo, hi;
            UNPACK2(lo, hi, acc[ii][j]);
            v[2 * ii][j]     = lo;
            v[2 * ii + 1][j] = hi;
        }

    #pragma unroll
    for (int i = 0; i < 8; i++) {
        int m = mBase + ty * 8 + i;
        if (m >= M) continue;
        float di = g_dinv[m];
        float ds = di * di;
        size_t base = (size_t)m * DHID + nBase + tx * 8;
        float4 h0 = make_float4(v[i][0], v[i][1], v[i][2], v[i][3]);
        float4 h1 = make_float4(v[i][4], v[i][5], v[i][6], v[i][7]);
        *reinterpret_cast<float4*>(g_h + base)     = h0;
        *reinterpret_cast<float4*>(g_h + base + 4) = h1;
        float4 a0 = make_float4(h0.x * ds, h0.y * ds, h0.z * ds, h0.w * ds);
        float4 a1 = make_float4(h1.x * ds, h1.y * ds, h1.z * ds, h1.w * ds);
        *reinterpret_cast<float4*>(g_agg + base)     = a0;
        *reinterpret_cast<float4*>(g_agg + base + 4) = a1;
    }
}

// ---------------------------------------------------------------------------
// Edge scatter: agg[dst] += h[src] * dinv[src]*dinv[dst]
// 64 threads per edge, one float4 + one red.v4 per thread.
// ---------------------------------------------------------------------------
__global__ __launch_bounds__(256)
void scatter_kernel(const int* __restrict__ src, const int* __restrict__ dst,
                    int E) {
    long long gid = (long long)blockIdx.x * blockDim.x + threadIdx.x;
    int e = (int)(gid >> 6);
    if (e >= E) return;
    int f = (int)gid & 63;
    int s = __ldg(src + e);
    int d = __ldg(dst + e);
    float norm = __ldg(g_dinv + s) * __ldg(g_dinv + d);
    float4 v = __ldg(reinterpret_cast<const float4*>(g_h) + (size_t)s * DH4 + f);
    float* addr = g_agg + ((size_t)d * DH4 + f) * 4;
    red_add_v4(addr, v.x * norm, v.y * norm, v.z * norm, v.w * norm);
}

// ---------------------------------------------------------------------------
// Bias (+ReLU) epilogue. TO_OUT=false writes g_x1, true writes param out.
// ---------------------------------------------------------------------------
template <bool RELU, bool TO_OUT>
__global__ __launch_bounds__(256)
void finish_kernel(const float* __restrict__ b, float* __restrict__ out,
                   int M) {
    int idx = blockIdx.x * blockDim.x + threadIdx.x;   // over M * 64 float4s
    if (idx >= M * DH4) return;
    int j4 = idx & (DH4 - 1);
    float4 a  = *(reinterpret_cast<const float4*>(g_agg) + idx);
    float4 bb = __ldg(reinterpret_cast<const float4*>(b) + j4);
    float4 r = make_float4(a.x + bb.x, a.y + bb.y, a.z + bb.z, a.w + bb.w);
    if (RELU) {
        r.x = fmaxf(r.x, 0.f); r.y = fmaxf(r.y, 0.f);
        r.z = fmaxf(r.z, 0.f); r.w = fmaxf(r.w, 0.f);
    }
    float4* dstp = TO_OUT ? reinterpret_cast<float4*>(out)
                          : reinterpret_cast<float4*>(g_x1);
    dstp[idx] = r;
}

// ---------------------------------------------------------------------------
// Launch
// ---------------------------------------------------------------------------
extern "C" void kernel_launch(void* const* d_in, const int* in_sizes, int n_in,
                              void* d_out, int out_size) {
    const float* x  = (const float*)d_in[0];
    const int*   ei = (const int*)  d_in[1];
    const float* W1 = (const float*)d_in[2];
    const float* b1 = (const float*)d_in[3];
    const float* W2 = (const float*)d_in[4];
    const float* b2 = (const float*)d_in[5];
    const float* W3 = (const float*)d_in[6];
    const float* b3 = (const float*)d_in[7];
    float* out = (float*)d_out;

    const int M = in_sizes[0] / DIN;       // 50000
    const int E = in_sizes[1] / 2;         // 500000
    const int* src = ei;
    const int* dst = ei + E;

    const int T = 256;
    // degrees -> dinv_sqrt
    deg_init_kernel  <<<(M + T - 1) / T, T>>>(M);
    deg_count_kernel <<<(E + T - 1) / T, T>>>(dst, E);
    deg_finish_kernel<<<(M + T - 1) / T, T>>>(M);

    dim3 gemmGrid(DHID / 128, (M + 127) / 128);          // (2, 391)
    long long sThreads = (long long)E * 64;
    int sBlocks = (int)((sThreads + T - 1) / T);
    int fBlocks = (M * DH4 + T - 1) / T;

    // layer 1: 128 -> 256, ReLU
    gemm_agg_kernel<DIN, false><<<gemmGrid, T>>>(x, W1, M);
    scatter_kernel<<<sBlocks, T>>>(src, dst, E);
    finish_kernel<true, false><<<fBlocks, T>>>(b1, nullptr, M);

    // layer 2: 256 -> 256, ReLU
    gemm_agg_kernel<DHID, true><<<gemmGrid, T>>>(nullptr, W2, M);
    scatter_kernel<<<sBlocks, T>>>(src, dst, E);
    finish_kernel<true, false><<<fBlocks, T>>>(b2, nullptr, M);

    // layer 3: 256 -> 256, no ReLU, write d_out
    gemm_agg_kernel<DHID, true><<<gemmGrid, T>>>(nullptr, W3, M);
    scatter_kernel<<<sBlocks, T>>>(src, dst, E);
    finish_kernel<false, true><<<fBlocks, T>>>(b3, out, M);
}

// round 4
// speedup vs baseline: 1.3740x; 1.3740x over previous
#include <cuda_runtime.h>
#include <cstdint>

// Problem constants (from reference)
#define NN      50000     // N_NODES
#define DIN     128
#define DHID    256
#define EMAX    500000

// ---------------------------------------------------------------------------
// Scratch (static device globals — no allocation in kernel_launch)
// ---------------------------------------------------------------------------
__device__ float g_h  [(size_t)NN * DHID];   // GEMM output (pre-aggregation)
__device__ float g_x1 [(size_t)NN * DHID];   // activation ping
__device__ float g_x2 [(size_t)NN * DHID];   // activation pong
__device__ float g_xa [(size_t)NN * DIN];    // aggregated input (layer 1)
__device__ float g_dinv[NN];                 // D^{-1/2} (deg incl self loop)
__device__ int   g_degi[NN];                 // in-degree histogram (no self loop)
__device__ int   g_rowptr[NN + 1];           // CSR row pointers (by dst)
__device__ int   g_cursor[NN];               // fill cursors
__device__ int   g_csrc[EMAX];               // CSR column (src) indices

// ---------------------------------------------------------------------------
// f32x2 packed-FMA helpers (FFMA2 — PTX-only on sm_103a)
// ---------------------------------------------------------------------------
#define FMA2(d, a, b) \
    asm("fma.rn.f32x2 %0, %1, %2, %0;" : "+l"(d) : "l"(a), "l"(b))
#define PACK2(d, lo, hi) \
    asm("mov.b64 %0, {%1, %2};" : "=l"(d) : "f"(lo), "f"(hi))
#define UNPACK2(lo, hi, d) \
    asm("mov.b64 {%0, %1}, %2;" : "=f"(lo), "=f"(hi) : "l"(d))

// ---------------------------------------------------------------------------
// Degree / normalization / CSR build
// ---------------------------------------------------------------------------
__global__ void deg_init_kernel(int n) {
    int i = blockIdx.x * blockDim.x + threadIdx.x;
    if (i < n) g_degi[i] = 0;
}

__global__ void deg_count_kernel(const int* __restrict__ dst, int E) {
    int i = blockIdx.x * blockDim.x + threadIdx.x;
    if (i < E) atomicAdd(&g_degi[dst[i]], 1);
}

__global__ void deg_finish_kernel(int n) {
    int i = blockIdx.x * blockDim.x + threadIdx.x;
    if (i < n) g_dinv[i] = rsqrtf((float)(g_degi[i] + 1));  // +1 self loop
}

// Single-block exclusive scan of g_degi -> g_rowptr / g_cursor.
__global__ __launch_bounds__(1024)
void scan_kernel(int n) {
    __shared__ int ssum[1024];
    int tid = threadIdx.x;
    int chunk = (n + 1023) >> 10;
    int begin = tid * chunk;
    int end   = begin + chunk;
    if (end > n) end = n;
    int s = 0;
    for (int i = begin; i < end; i++) s += g_degi[i];
    ssum[tid] = s;
    __syncthreads();
    // Kogge–Stone inclusive scan of chunk sums
    for (int off = 1; off < 1024; off <<= 1) {
        int t = 0;
        if (tid >= off) t = ssum[tid - off];
        __syncthreads();
        if (tid >= off) ssum[tid] += t;
        __syncthreads();
    }
    int run = ssum[tid] - s;   // exclusive prefix for this chunk
    for (int i = begin; i < end; i++) {
        g_rowptr[i] = run;
        g_cursor[i] = run;
        run += g_degi[i];
    }
    if (tid == 1023) g_rowptr[n] = ssum[1023];
}

__global__ void fill_kernel(const int* __restrict__ src,
                            const int* __restrict__ dst, int E) {
    int i = blockIdx.x * blockDim.x + threadIdx.x;
    if (i < E) {
        int d = dst[i];
        int pos = atomicAdd(&g_cursor[d], 1);
        g_csrc[pos] = src[i];
    }
}

// ---------------------------------------------------------------------------
// CSR gather-aggregate (+ optional bias / ReLU epilogue):
//   Out[d] = RELU( (sum_{s in N(d)} H[s]*dinv[s] + H[d]*dinv[d]) * dinv[d] + b )
// D/4 threads per row, float4 per thread. No atomics.
// ---------------------------------------------------------------------------
template <int D, bool BIAS, bool RELU>
__global__ __launch_bounds__(256)
void gather_kernel(const float* __restrict__ H, const float* __restrict__ bias,
                   float* __restrict__ Out, int M) {
    constexpr int TPR = D / 4;
    int gid = blockIdx.x * blockDim.x + threadIdx.x;
    int d = gid / TPR;
    if (d >= M) return;
    int f = gid % TPR;
    const float4* __restrict__ H4 = reinterpret_cast<const float4*>(H);

    float dd = __ldg(g_dinv + d);
    int beg = __ldg(g_rowptr + d);
    int end = __ldg(g_rowptr + d + 1);

    // self loop seeded
    float4 acc = __ldg(&H4[(size_t)d * TPR + f]);
    acc.x *= dd; acc.y *= dd; acc.z *= dd; acc.w *= dd;

    #pragma unroll 4
    for (int e = beg; e < end; e++) {
        int s = __ldg(g_csrc + e);
        float w = __ldg(g_dinv + s);
        float4 v = __ldg(&H4[(size_t)s * TPR + f]);
        acc.x = fmaf(v.x, w, acc.x);
        acc.y = fmaf(v.y, w, acc.y);
        acc.z = fmaf(v.z, w, acc.z);
        acc.w = fmaf(v.w, w, acc.w);
    }
    acc.x *= dd; acc.y *= dd; acc.z *= dd; acc.w *= dd;

    if (BIAS) {
        float4 bb = __ldg(reinterpret_cast<const float4*>(bias) + f);
        acc.x += bb.x; acc.y += bb.y; acc.z += bb.z; acc.w += bb.w;
    }
    if (RELU) {
        acc.x = fmaxf(acc.x, 0.f); acc.y = fmaxf(acc.y, 0.f);
        acc.z = fmaxf(acc.z, 0.f); acc.w = fmaxf(acc.w, 0.f);
    }
    reinterpret_cast<float4*>(Out)[(size_t)d * TPR + f] = acc;
}

// ---------------------------------------------------------------------------
// Double-buffered fp32 GEMM: Out = X @ W (+ bias, ReLU optional)
// BM=128, BN=128, BK=8, 256 threads, 8x8 per thread via f32x2 row-pairs.
// ---------------------------------------------------------------------------
template <int K, bool BIAS, bool RELU>
__global__ __launch_bounds__(256)
void gemm_kernel(const float* __restrict__ X, const float* __restrict__ W,
                 const float* __restrict__ bias, float* __restrict__ Out,
                 int M) {
    constexpr int BM = 128, BN = 128, BK = 8;
    __shared__ float As[2][BK][BM];
    __shared__ float Bs[2][BK][BN];

    const int tid   = threadIdx.x;
    const int mBase = blockIdx.y * BM;
    const int nBase = blockIdx.x * BN;
    const int ty = tid >> 4;          // 8 rows each
    const int tx = tid & 15;          // 8 cols each

    const int aRow = tid >> 1;
    const int aK   = (tid & 1) * 4;
    const int bK   = tid >> 5;
    const int bCol = (tid & 31) * 4;

    const int mA = mBase + aRow;
    const float* __restrict__ Aptr = X + (size_t)mA * K + aK;
    const float* __restrict__ Bptr = W + (size_t)bK * DHID + nBase + bCol;

    unsigned long long acc[4][8];
    #pragma unroll
    for (int ii = 0; ii < 4; ii++)
        #pragma unroll
        for (int j = 0; j < 8; j++) acc[ii][j] = 0ULL;

    // prologue: tile 0 -> buf 0
    float4 av = make_float4(0.f, 0.f, 0.f, 0.f);
    if (mA < M) av = *reinterpret_cast<const float4*>(Aptr);
    float4 bv = *reinterpret_cast<const float4*>(Bptr);
    As[0][aK + 0][aRow] = av.x;
    As[0][aK + 1][aRow] = av.y;
    As[0][aK + 2][aRow] = av.z;
    As[0][aK + 3][aRow] = av.w;
    *reinterpret_cast<float4*>(&Bs[0][bK][bCol]) = bv;
    __syncthreads();

    int buf = 0;
    #pragma unroll 1
    for (int k0 = 0; k0 < K; k0 += BK) {
        const bool has_next = (k0 + BK) < K;
        if (has_next) {
            av = make_float4(0.f, 0.f, 0.f, 0.f);
            if (mA < M)
                av = *reinterpret_cast<const float4*>(Aptr + k0 + BK);
            bv = *reinterpret_cast<const float4*>(
                Bptr + (size_t)(k0 + BK) * DHID);
        }

        #pragma unroll
        for (int k = 0; k < BK; k++) {
            unsigned long long a2[4];
            #pragma unroll
            for (int ii = 0; ii < 4; ii++)
                a2[ii] = *reinterpret_cast<const unsigned long long*>(
                    &As[buf][k][ty * 8 + 2 * ii]);
            float4 b0 = *reinterpret_cast<const float4*>(&Bs[buf][k][tx * 8]);
            float4 b1 = *reinterpret_cast<const float4*>(&Bs[buf][k][tx * 8 + 4]);
            unsigned long long bd[8];
            PACK2(bd[0], b0.x, b0.x);  PACK2(bd[1], b0.y, b0.y);
            PACK2(bd[2], b0.z, b0.z);  PACK2(bd[3], b0.w, b0.w);
            PACK2(bd[4], b1.x, b1.x);  PACK2(bd[5], b1.y, b1.y);
            PACK2(bd[6], b1.z, b1.z);  PACK2(bd[7], b1.w, b1.w);
            #pragma unroll
            for (int ii = 0; ii < 4; ii++)
                #pragma unroll
                for (int j = 0; j < 8; j++)
                    FMA2(acc[ii][j], a2[ii], bd[j]);
        }

        if (has_next) {
            int nb = buf ^ 1;
            As[nb][aK + 0][aRow] = av.x;
            As[nb][aK + 1][aRow] = av.y;
            As[nb][aK + 2][aRow] = av.z;
            As[nb][aK + 3][aRow] = av.w;
            *reinterpret_cast<float4*>(&Bs[nb][bK][bCol]) = bv;
        }
        __syncthreads();
        buf ^= 1;
    }

    // epilogue
    float v[8][8];
    #pragma unroll
    for (int ii = 0; ii < 4; ii++)
        #pragma unroll
        for (int j = 0; j < 8; j++) {
            float lo, hi;
            UNPACK2(lo, hi, acc[ii][j]);
            v[2 * ii][j]     = lo;
            v[2 * ii + 1][j] = hi;
        }

    float4 bb0 = make_float4(0.f, 0.f, 0.f, 0.f);
    float4 bb1 = make_float4(0.f, 0.f, 0.f, 0.f);
    if (BIAS) {
        bb0 = __ldg(reinterpret_cast<const float4*>(bias + nBase + tx * 8));
        bb1 = __ldg(reinterpret_cast<const float4*>(bias + nBase + tx * 8 + 4));
    }

    #pragma unroll
    for (int i = 0; i < 8; i++) {
        int m = mBase + ty * 8 + i;
        if (m >= M) continue;
        float4 h0 = make_float4(v[i][0], v[i][1], v[i][2], v[i][3]);
        float4 h1 = make_float4(v[i][4], v[i][5], v[i][6], v[i][7]);
        if (BIAS) {
            h0.x += bb0.x; h0.y += bb0.y; h0.z += bb0.z; h0.w += bb0.w;
            h1.x += bb1.x; h1.y += bb1.y; h1.z += bb1.z; h1.w += bb1.w;
        }
        if (RELU) {
            h0.x = fmaxf(h0.x, 0.f); h0.y = fmaxf(h0.y, 0.f);
            h0.z = fmaxf(h0.z, 0.f); h0.w = fmaxf(h0.w, 0.f);
            h1.x = fmaxf(h1.x, 0.f); h1.y = fmaxf(h1.y, 0.f);
            h1.z = fmaxf(h1.z, 0.f); h1.w = fmaxf(h1.w, 0.f);
        }
        size_t base = (size_t)m * DHID + nBase + tx * 8;
        *reinterpret_cast<float4*>(Out + base)     = h0;
        *reinterpret_cast<float4*>(Out + base + 4) = h1;
    }
}

// ---------------------------------------------------------------------------
// Launch:
//   layer1 (linearity): xa = agg(x); x1 = relu(xa@W1 + b1)
//   layer2: h = x1@W2;  x2 = relu(agg(h) + b2)
//   layer3: h = x2@W3;  out = agg(h) + b3
// ---------------------------------------------------------------------------
extern "C" void kernel_launch(void* const* d_in, const int* in_sizes, int n_in,
                              void* d_out, int out_size) {
    const float* x  = (const float*)d_in[0];
    const int*   ei = (const int*)  d_in[1];
    const float* W1 = (const float*)d_in[2];
    const float* b1 = (const float*)d_in[3];
    const float* W2 = (const float*)d_in[4];
    const float* b2 = (const float*)d_in[5];
    const float* W3 = (const float*)d_in[6];
    const float* b3 = (const float*)d_in[7];
    float* out = (float*)d_out;

    const int M = in_sizes[0] / DIN;       // 50000
    const int E = in_sizes[1] / 2;         // 500000
    const int* src = ei;
    const int* dst = ei + E;

    const int T = 256;
    // degrees + CSR build
    deg_init_kernel  <<<(M + T - 1) / T, T>>>(M);
    deg_count_kernel <<<(E + T - 1) / T, T>>>(dst, E);
    deg_finish_kernel<<<(M + T - 1) / T, T>>>(M);
    scan_kernel      <<<1, 1024>>>(M);
    fill_kernel      <<<(E + T - 1) / T, T>>>(src, dst, E);

    dim3 gemmGrid(DHID / 128, (M + 127) / 128);          // (2, 391)
    int g128 = (M * (DIN  / 4) + T - 1) / T;
    int g256 = (M * (DHID / 4) + T - 1) / T;

    float* g_xa_p = nullptr, *g_x1_p = nullptr, *g_x2_p = nullptr, *g_h_p = nullptr;
    cudaGetSymbolAddress((void**)&g_xa_p, g_xa);
    cudaGetSymbolAddress((void**)&g_x1_p, g_x1);
    cudaGetSymbolAddress((void**)&g_x2_p, g_x2);
    cudaGetSymbolAddress((void**)&g_h_p,  g_h);

    // layer 1: pre-aggregate input (128 dims), GEMM fused bias+ReLU
    gather_kernel<DIN, false, false><<<g128, T>>>(x, nullptr, g_xa_p, M);
    gemm_kernel<DIN, true, true><<<gemmGrid, T>>>(g_xa_p, W1, b1, g_x1_p, M);

    // layer 2
    gemm_kernel<DHID, false, false><<<gemmGrid, T>>>(g_x1_p, W2, nullptr, g_h_p, M);
    gather_kernel<DHID, true, true><<<g256, T>>>(g_h_p, b2, g_x2_p, M);

    // layer 3
    gemm_kernel<DHID, false, false><<<gemmGrid, T>>>(g_x2_p, W3, nullptr, g_h_p, M);
    gather_kernel<DHID, true, false><<<g256, T>>>(g_h_p, b3, out, M);
}

// round 6
// speedup vs baseline: 1.4886x; 1.0834x over previous
#include <cuda_runtime.h>
#include <cstdint>

// Problem constants (from reference)
#define NN      50000     // N_NODES
#define DIN     128
#define DHID    256
#define EMAX    500000

#define SCAN_E    512                           // elements per scan block
#define SCAN_B    ((NN + SCAN_E - 1) / SCAN_E)  // 98 blocks

typedef unsigned long long ull;

// ---------------------------------------------------------------------------
// Scratch (static device globals — no allocation in kernel_launch)
// ---------------------------------------------------------------------------
__device__ float g_h  [(size_t)NN * DHID];   // GEMM output (pre-aggregation)
__device__ float g_x1 [(size_t)NN * DHID];   // activation ping
__device__ float g_x2 [(size_t)NN * DHID];   // activation pong
__device__ float g_xa [(size_t)NN * DIN];    // aggregated input (layer 1)
__device__ float g_dinv[NN];                 // D^{-1/2} (deg incl self loop)
__device__ int   g_degi[NN];                 // in-degree histogram (no self loop)
__device__ int   g_rowptr[NN + 1];           // CSR row pointers (by dst)
__device__ int   g_cursor[NN];               // fill cursors
__device__ int   g_csrc[EMAX];               // CSR column (src) indices
__device__ int   g_bsum[SCAN_B];             // per-block degree sums
__device__ int   g_boff[SCAN_B];             // per-block exclusive offsets

// ---------------------------------------------------------------------------
// f32x2 packed-FMA helpers (FFMA2 — PTX-only on sm_103a)
// ---------------------------------------------------------------------------
#define FMA2(d, a, b) \
    asm("fma.rn.f32x2 %0, %1, %2, %0;" : "+l"(d) : "l"(a), "l"(b))
#define PACK2(d, lo, hi) \
    asm("mov.b64 %0, {%1, %2};" : "=l"(d) : "f"(lo), "f"(hi))
#define UNPACK2(lo, hi, d) \
    asm("mov.b64 {%0, %1}, %2;" : "=f"(lo), "=f"(hi) : "l"(d))

// ---------------------------------------------------------------------------
// Degree histogram
// ---------------------------------------------------------------------------
__global__ void deg_init_kernel(int n) {
    int i = blockIdx.x * blockDim.x + threadIdx.x;
    if (i < n) g_degi[i] = 0;
}

__global__ void deg_count_kernel(const int* __restrict__ dst, int E) {
    int i = blockIdx.x * blockDim.x + threadIdx.x;
    if (i < E) atomicAdd(&g_degi[dst[i]], 1);
}

// ---------------------------------------------------------------------------
// Parallel 3-stage exclusive scan of g_degi -> rowptr/cursor (+dinv fused)
// ---------------------------------------------------------------------------
__device__ __forceinline__ int block_incl_scan_128(int s, int tid) {
    __shared__ int ws[5];
    int lane = tid & 31, w = tid >> 5;
    #pragma unroll
    for (int o = 1; o < 32; o <<= 1) {
        int t = __shfl_up_sync(0xffffffffu, s, o);
        if (lane >= o) s += t;
    }
    if (lane == 31) ws[w + 1] = s;
    __syncthreads();
    if (tid == 0) { ws[0] = 0; ws[2] += ws[1]; ws[3] += ws[2]; ws[4] += ws[3]; }
    __syncthreads();
    return s + ws[w];
}

// stage 1: per-block sums (98 blocks x 128 threads, 4 ints each)
__global__ __launch_bounds__(128)
void bsum_kernel(int n) {
    int tid = threadIdx.x;
    int base = blockIdx.x * SCAN_E + tid * 4;
    int4 v = make_int4(0, 0, 0, 0);
    if (base < n) v = *reinterpret_cast<const int4*>(&g_degi[base]);
    int s = block_incl_scan_128(v.x + v.y + v.z + v.w, tid);
    if (tid == 127) g_bsum[blockIdx.x] = s;
}

// stage 2: scan the 98 block sums (1 block)
__global__ __launch_bounds__(128)
void bscan_kernel(int n, int nblk) {
    int tid = threadIdx.x;
    int v = (tid < nblk) ? g_bsum[tid] : 0;
    int incl = block_incl_scan_128(v, tid);
    if (tid < nblk) g_boff[tid] = incl - v;
    if (tid == nblk - 1) g_rowptr[n] = incl;   // total edge count
}

// stage 3: local scans + rowptr/cursor/dinv writes
__global__ __launch_bounds__(128)
void bfill_kernel(int n) {
    int tid = threadIdx.x;
    int base = blockIdx.x * SCAN_E + tid * 4;
    int4 v = make_int4(0, 0, 0, 0);
    if (base < n) v = *reinterpret_cast<const int4*>(&g_degi[base]);
    int s = v.x + v.y + v.z + v.w;
    int incl = block_incl_scan_128(s, tid);
    int ex = incl - s + g_boff[blockIdx.x];
    if (base < n) {
        int4 r;
        r.x = ex;
        r.y = r.x + v.x;
        r.z = r.y + v.y;
        r.w = r.z + v.z;
        *reinterpret_cast<int4*>(&g_rowptr[base]) = r;
        *reinterpret_cast<int4*>(&g_cursor[base]) = r;
        float4 dv;
        dv.x = rsqrtf((float)(v.x + 1));   // +1 self loop
        dv.y = rsqrtf((float)(v.y + 1));
        dv.z = rsqrtf((float)(v.z + 1));
        dv.w = rsqrtf((float)(v.w + 1));
        *reinterpret_cast<float4*>(&g_dinv[base]) = dv;
    }
}

__global__ void fill_kernel(const int* __restrict__ src,
                            const int* __restrict__ dst, int E) {
    int i = blockIdx.x * blockDim.x + threadIdx.x;
    if (i < E) {
        int d = dst[i];
        int pos = atomicAdd(&g_cursor[d], 1);
        g_csrc[pos] = src[i];
    }
}

// ---------------------------------------------------------------------------
// CSR gather-aggregate (+ optional bias / ReLU epilogue):
//   Out[d] = RELU( (sum_{s in N(d)} H[s]*dinv[s] + H[d]*dinv[d]) * dinv[d] + b )
// ---------------------------------------------------------------------------
template <int D, bool BIAS, bool RELU>
__global__ __launch_bounds__(256)
void gather_kernel(const float* __restrict__ H, const float* __restrict__ bias,
                   float* __restrict__ Out, int M) {
    constexpr int TPR = D / 4;
    int gid = blockIdx.x * blockDim.x + threadIdx.x;
    int d = gid / TPR;
    if (d >= M) return;
    int f = gid % TPR;
    const float4* __restrict__ H4 = reinterpret_cast<const float4*>(H);

    float dd = __ldg(g_dinv + d);
    int beg = __ldg(g_rowptr + d);
    int end = __ldg(g_rowptr + d + 1);

    float4 acc = __ldg(&H4[(size_t)d * TPR + f]);   // self loop seed
    acc.x *= dd; acc.y *= dd; acc.z *= dd; acc.w *= dd;

    #pragma unroll 4
    for (int e = beg; e < end; e++) {
        int s = __ldg(g_csrc + e);
        float w = __ldg(g_dinv + s);
        float4 v = __ldg(&H4[(size_t)s * TPR + f]);
        acc.x = fmaf(v.x, w, acc.x);
        acc.y = fmaf(v.y, w, acc.y);
        acc.z = fmaf(v.z, w, acc.z);
        acc.w = fmaf(v.w, w, acc.w);
    }
    acc.x *= dd; acc.y *= dd; acc.z *= dd; acc.w *= dd;

    if (BIAS) {
        float4 bb = __ldg(reinterpret_cast<const float4*>(bias) + f);
        acc.x += bb.x; acc.y += bb.y; acc.z += bb.z; acc.w += bb.w;
    }
    if (RELU) {
        acc.x = fmaxf(acc.x, 0.f); acc.y = fmaxf(acc.y, 0.f);
        acc.z = fmaxf(acc.z, 0.f); acc.w = fmaxf(acc.w, 0.f);
    }
    reinterpret_cast<float4*>(Out)[(size_t)d * TPR + f] = acc;
}

// ---------------------------------------------------------------------------
// Double-buffered fp32 GEMM, FFMA2 inner loop with zero register-shuffle movs.
// A staged DUPLICATED in smem ((a,a) pairs); accumulators pair over columns.
// Thread (ty, tx): rows ty*8..+7, cols {tx*4..+3} u {64+tx*4..+3}.
// ---------------------------------------------------------------------------
template <int K, bool BIAS, bool RELU>
__global__ __launch_bounds__(256, 2)
void gemm_kernel(const float* __restrict__ X, const float* __restrict__ W,
                 const float* __restrict__ bias, float* __restrict__ Out,
                 int M) {
    constexpr int BM = 128, BN = 128, BK = 8;
    __shared__ float As2[2][BK][BM * 2];   // duplicated (a,a) pairs
    __shared__ float Bs [2][BK][BN];

    const int tid   = threadIdx.x;
    const int mBase = blockIdx.y * BM;
    const int nBase = blockIdx.x * BN;
    const int ty = tid >> 4;
    const int tx = tid & 15;

    const int aRow = tid >> 1;
    const int aK   = (tid & 1) * 4;
    const int bK   = tid >> 5;
    const int bCol = (tid & 31) * 4;

    const int mA = mBase + aRow;
    const float* __restrict__ Aptr = X + (size_t)mA * K + aK;
    const float* __restrict__ Bptr = W + (size_t)bK * DHID + nBase + bCol;

    ull acc[8][4];
    #pragma unroll
    for (int i = 0; i < 8; i++)
        #pragma unroll
        for (int j = 0; j < 4; j++) acc[i][j] = 0ULL;

    // prologue: tile 0 -> buf 0
    float4 av = make_float4(0.f, 0.f, 0.f, 0.f);
    if (mA < M) av = *reinterpret_cast<const float4*>(Aptr);
    float4 bv = *reinterpret_cast<const float4*>(Bptr);
    {
        ull p;
        PACK2(p, av.x, av.x); *reinterpret_cast<ull*>(&As2[0][aK + 0][aRow * 2]) = p;
        PACK2(p, av.y, av.y); *reinterpret_cast<ull*>(&As2[0][aK + 1][aRow * 2]) = p;
        PACK2(p, av.z, av.z); *reinterpret_cast<ull*>(&As2[0][aK + 2][aRow * 2]) = p;
        PACK2(p, av.w, av.w); *reinterpret_cast<ull*>(&As2[0][aK + 3][aRow * 2]) = p;
        *reinterpret_cast<float4*>(&Bs[0][bK][bCol]) = bv;
    }
    __syncthreads();

    int buf = 0;
    #pragma unroll 1
    for (int k0 = 0; k0 < K; k0 += BK) {
        const bool has_next = (k0 + BK) < K;
        if (has_next) {
            av = make_float4(0.f, 0.f, 0.f, 0.f);
            if (mA < M)
                av = *reinterpret_cast<const float4*>(Aptr + k0 + BK);
            bv = *reinterpret_cast<const float4*>(Bptr + (size_t)(k0 + BK) * DHID);
        }

        #pragma unroll
        for (int k = 0; k < BK; k++) {
            ulonglong2 a01 = *reinterpret_cast<const ulonglong2*>(
                &As2[buf][k][(ty * 8 + 0) * 2]);
            ulonglong2 a23 = *reinterpret_cast<const ulonglong2*>(
                &As2[buf][k][(ty * 8 + 2) * 2]);
            ulonglong2 a45 = *reinterpret_cast<const ulonglong2*>(
                &As2[buf][k][(ty * 8 + 4) * 2]);
            ulonglong2 a67 = *reinterpret_cast<const ulonglong2*>(
                &As2[buf][k][(ty * 8 + 6) * 2]);
            ulonglong2 b01 = *reinterpret_cast<const ulonglong2*>(
                &Bs[buf][k][tx * 4]);
            ulonglong2 b23 = *reinterpret_cast<const ulonglong2*>(
                &Bs[buf][k][64 + tx * 4]);
            ull a[8] = {a01.x, a01.y, a23.x, a23.y, a45.x, a45.y, a67.x, a67.y};
            ull b[4] = {b01.x, b01.y, b23.x, b23.y};
            #pragma unroll
            for (int i = 0; i < 8; i++)
                #pragma unroll
                for (int j = 0; j < 4; j++)
                    FMA2(acc[i][j], a[i], b[j]);
        }

        if (has_next) {
            int nb = buf ^ 1;
            ull p;
            PACK2(p, av.x, av.x); *reinterpret_cast<ull*>(&As2[nb][aK + 0][aRow * 2]) = p;
            PACK2(p, av.y, av.y); *reinterpret_cast<ull*>(&As2[nb][aK + 1][aRow * 2]) = p;
            PACK2(p, av.z, av.z); *reinterpret_cast<ull*>(&As2[nb][aK + 2][aRow * 2]) = p;
            PACK2(p, av.w, av.w); *reinterpret_cast<ull*>(&As2[nb][aK + 3][aRow * 2]) = p;
            *reinterpret_cast<float4*>(&Bs[nb][bK][bCol]) = bv;
        }
        __syncthreads();
        buf ^= 1;
    }

    // epilogue
    float4 bb0 = make_float4(0.f, 0.f, 0.f, 0.f);
    float4 bb1 = make_float4(0.f, 0.f, 0.f, 0.f);
    if (BIAS) {
        bb0 = __ldg(reinterpret_cast<const float4*>(bias + nBase + tx * 4));
        bb1 = __ldg(reinterpret_cast<const float4*>(bias + nBase + 64 + tx * 4));
    }

    #pragma unroll
    for (int i = 0; i < 8; i++) {
        int m = mBase + ty * 8 + i;
        if (m >= M) continue;
        float4 h0, h1;
        UNPACK2(h0.x, h0.y, acc[i][0]);
        UNPACK2(h0.z, h0.w, acc[i][1]);
        UNPACK2(h1.x, h1.y, acc[i][2]);
        UNPACK2(h1.z, h1.w, acc[i][3]);
        if (BIAS) {
            h0.x += bb0.x; h0.y += bb0.y; h0.z += bb0.z; h0.w += bb0.w;
            h1.x += bb1.x; h1.y += bb1.y; h1.z += bb1.z; h1.w += bb1.w;
        }
        if (RELU) {
            h0.x = fmaxf(h0.x, 0.f); h0.y = fmaxf(h0.y, 0.f);
            h0.z = fmaxf(h0.z, 0.f); h0.w = fmaxf(h0.w, 0.f);
            h1.x = fmaxf(h1.x, 0.f); h1.y = fmaxf(h1.y, 0.f);
            h1.z = fmaxf(h1.z, 0.f); h1.w = fmaxf(h1.w, 0.f);
        }
        size_t base = (size_t)m * DHID + nBase;
        *reinterpret_cast<float4*>(Out + base + tx * 4)      = h0;
        *reinterpret_cast<float4*>(Out + base + 64 + tx * 4) = h1;
    }
}

// ---------------------------------------------------------------------------
// Launch:
//   layer1 (linearity): xa = agg(x); x1 = relu(xa@W1 + b1)
//   layer2: h = x1@W2;  x2 = relu(agg(h) + b2)
//   layer3: h = x2@W3;  out = agg(h) + b3
// ---------------------------------------------------------------------------
extern "C" void kernel_launch(void* const* d_in, const int* in_sizes, int n_in,
                              void* d_out, int out_size) {
    const float* x  = (const float*)d_in[0];
    const int*   ei = (const int*)  d_in[1];
    const float* W1 = (const float*)d_in[2];
    const float* b1 = (const float*)d_in[3];
    const float* W2 = (const float*)d_in[4];
    const float* b2 = (const float*)d_in[5];
    const float* W3 = (const float*)d_in[6];
    const float* b3 = (const float*)d_in[7];
    float* out = (float*)d_out;

    const int M = in_sizes[0] / DIN;       // 50000
    const int E = in_sizes[1] / 2;         // 500000
    const int* src = ei;
    const int* dst = ei + E;

    const int T = 256;
    // degrees + CSR build (parallel scan)
    deg_init_kernel <<<(M + T - 1) / T, T>>>(M);
    deg_count_kernel<<<(E + T - 1) / T, T>>>(dst, E);
    bsum_kernel     <<<SCAN_B, 128>>>(M);
    bscan_kernel    <<<1, 128>>>(M, SCAN_B);
    bfill_kernel    <<<SCAN_B, 128>>>(M);
    fill_kernel     <<<(E + T - 1) / T, T>>>(src, dst, E);

    dim3 gemmGrid(DHID / 128, (M + 127) / 128);          // (2, 391)
    int g128 = (M * (DIN  / 4) + T - 1) / T;
    int g256 = (M * (DHID / 4) + T - 1) / T;

    float *g_xa_p = nullptr, *g_x1_p = nullptr, *g_x2_p = nullptr, *g_h_p = nullptr;
    cudaGetSymbolAddress((void**)&g_xa_p, g_xa);
    cudaGetSymbolAddress((void**)&g_x1_p, g_x1);
    cudaGetSymbolAddress((void**)&g_x2_p, g_x2);
    cudaGetSymbolAddress((void**)&g_h_p,  g_h);

    // layer 1: pre-aggregate input (128 dims), GEMM fused bias+ReLU
    gather_kernel<DIN, false, false><<<g128, T>>>(x, nullptr, g_xa_p, M);
    gemm_kernel<DIN, true, true><<<gemmGrid, T>>>(g_xa_p, W1, b1, g_x1_p, M);

    // layer 2
    gemm_kernel<DHID, false, false><<<gemmGrid, T>>>(g_x1_p, W2, nullptr, g_h_p, M);
    gather_kernel<DHID, true, true><<<g256, T>>>(g_h_p, b2, g_x2_p, M);

    // layer 3
    gemm_kernel<DHID, false, false><<<gemmGrid, T>>>(g_x2_p, W3, nullptr, g_h_p, M);
    gather_kernel<DHID, true, false><<<g256, T>>>(g_h_p, b3, out, M);
}